// round 1
// baseline (speedup 1.0000x reference)
#include <cuda_runtime.h>
#include <math.h>

#define H        512
#define NDRONES  16384
#define NPAIRS   131072

// ---------------- scratch (static __device__ per allocation rules) ----------
__device__ float g_ABcomb[H * 2 * H];        // [512][1024]: cols 0:512 = W1a-W1c, 512:1024 = W1b+W1c
__device__ float g_UV[NDRONES * 2 * H];      // [16384][1024]: row i = [U_i | V_i]
__device__ float g_partial[4 * NPAIRS];      // per-N-block partial logits

// ---------------- kernel A: combine W1 blocks --------------------------------
__global__ void combine_w1(const float* __restrict__ W1) {
    int idx = blockIdx.x * blockDim.x + threadIdx.x;
    if (idx >= H * H) return;
    int k = idx / H, n = idx % H;
    float wa = W1[(size_t)k * H + n];
    float wb = W1[(size_t)(H + k) * H + n];
    float wc = W1[(size_t)(2 * H + k) * H + n];
    g_ABcomb[(size_t)k * (2 * H) + n]     = wa - wc;   // src coeff
    g_ABcomb[(size_t)k * (2 * H) + H + n] = wb + wc;   // dst coeff
}

// ---------------- kernel B: UV = E @ ABcomb  (16384 x 512 x 1024) -----------
__global__ __launch_bounds__(256) void uv_gemm(const float* __restrict__ E) {
    __shared__ __align__(16) float As[16 * 128];
    __shared__ __align__(16) float Bs[16 * 128];
    int t  = threadIdx.x;
    int tx = t & 15, ty = t >> 4;
    int m0 = blockIdx.x * 128;
    int n0 = blockIdx.y * 128;

    float acc[8][8];
#pragma unroll
    for (int i = 0; i < 8; i++)
#pragma unroll
        for (int j = 0; j < 8; j++) acc[i][j] = 0.f;

    int lm  = t >> 1;
    int lkk = (t & 1) * 8;
    const float* arow = E + (size_t)(m0 + lm) * H + lkk;

    for (int k0 = 0; k0 < H; k0 += 16) {
        // load A tile (transposed into smem)
        {
            float4 a0 = *(const float4*)(arow + k0);
            float4 a1 = *(const float4*)(arow + k0 + 4);
            As[(lkk + 0) * 128 + lm] = a0.x;
            As[(lkk + 1) * 128 + lm] = a0.y;
            As[(lkk + 2) * 128 + lm] = a0.z;
            As[(lkk + 3) * 128 + lm] = a0.w;
            As[(lkk + 4) * 128 + lm] = a1.x;
            As[(lkk + 5) * 128 + lm] = a1.y;
            As[(lkk + 6) * 128 + lm] = a1.z;
            As[(lkk + 7) * 128 + lm] = a1.w;
        }
        // load B tile
#pragma unroll
        for (int j = 0; j < 2; j++) {
            int idx4 = t * 2 + j;
            int kk = idx4 >> 5;
            int n4 = (idx4 & 31) * 4;
            float4 b = *(const float4*)(g_ABcomb + (size_t)(k0 + kk) * (2 * H) + n0 + n4);
            *(float4*)(Bs + kk * 128 + n4) = b;
        }
        __syncthreads();
#pragma unroll
        for (int kk = 0; kk < 16; kk++) {
            float a[8], b[8];
            *(float4*)(a)     = *(const float4*)(As + kk * 128 + ty * 8);
            *(float4*)(a + 4) = *(const float4*)(As + kk * 128 + ty * 8 + 4);
            *(float4*)(b)     = *(const float4*)(Bs + kk * 128 + tx * 8);
            *(float4*)(b + 4) = *(const float4*)(Bs + kk * 128 + tx * 8 + 4);
#pragma unroll
            for (int i = 0; i < 8; i++)
#pragma unroll
                for (int j = 0; j < 8; j++) acc[i][j] = fmaf(a[i], b[j], acc[i][j]);
        }
        __syncthreads();
    }
#pragma unroll
    for (int i = 0; i < 8; i++) {
        float* p = g_UV + (size_t)(m0 + ty * 8 + i) * (2 * H) + n0 + tx * 8;
        *(float4*)(p)     = make_float4(acc[i][0], acc[i][1], acc[i][2], acc[i][3]);
        *(float4*)(p + 4) = make_float4(acc[i][4], acc[i][5], acc[i][6], acc[i][7]);
    }
}

// ---------------- kernel C: per-pair GEMM + fused epilogue --------------------
// acc = (E[src] .* E[dst]) @ W1d ; h = relu(acc + U[src] + V[dst] + b1)
// partial[nblk][pair] = sum_n h[n] * W2[n]   (n within this 128-wide N block)
__global__ __launch_bounds__(256) void pair_kernel(
    const float* __restrict__ E, const int* __restrict__ rel,
    const float* __restrict__ W1, const float* __restrict__ b1,
    const float* __restrict__ W2)
{
    __shared__ __align__(16) float As[16 * 128];
    __shared__ __align__(16) float Bs[16 * 128];
    __shared__ int ssrc[128], sdst[128];

    int t  = threadIdx.x;
    int tx = t & 15, ty = t >> 4;
    int p0 = blockIdx.x * 128;
    int n0 = blockIdx.y * 128;

    if (t < 128) {
        ssrc[t] = rel[(size_t)(p0 + t) * 2 + 0];
        sdst[t] = rel[(size_t)(p0 + t) * 2 + 1];
    }
    __syncthreads();

    const float* Cmat = W1 + (size_t)(3 * H) * H;   // rows 1536..2047

    float acc[8][8];
#pragma unroll
    for (int i = 0; i < 8; i++)
#pragma unroll
        for (int j = 0; j < 8; j++) acc[i][j] = 0.f;

    int lm  = t >> 1;
    int lkk = (t & 1) * 8;
    const float* srow = E + (size_t)ssrc[lm] * H + lkk;
    const float* drow = E + (size_t)sdst[lm] * H + lkk;

    for (int k0 = 0; k0 < H; k0 += 16) {
        // gather src/dst rows, form elementwise product into A tile
        {
            float4 s0 = *(const float4*)(srow + k0);
            float4 s1 = *(const float4*)(srow + k0 + 4);
            float4 d0 = *(const float4*)(drow + k0);
            float4 d1 = *(const float4*)(drow + k0 + 4);
            As[(lkk + 0) * 128 + lm] = s0.x * d0.x;
            As[(lkk + 1) * 128 + lm] = s0.y * d0.y;
            As[(lkk + 2) * 128 + lm] = s0.z * d0.z;
            As[(lkk + 3) * 128 + lm] = s0.w * d0.w;
            As[(lkk + 4) * 128 + lm] = s1.x * d1.x;
            As[(lkk + 5) * 128 + lm] = s1.y * d1.y;
            As[(lkk + 6) * 128 + lm] = s1.z * d1.z;
            As[(lkk + 7) * 128 + lm] = s1.w * d1.w;
        }
#pragma unroll
        for (int j = 0; j < 2; j++) {
            int idx4 = t * 2 + j;
            int kk = idx4 >> 5;
            int n4 = (idx4 & 31) * 4;
            float4 b = *(const float4*)(Cmat + (size_t)(k0 + kk) * H + n0 + n4);
            *(float4*)(Bs + kk * 128 + n4) = b;
        }
        __syncthreads();
#pragma unroll
        for (int kk = 0; kk < 16; kk++) {
            float a[8], b[8];
            *(float4*)(a)     = *(const float4*)(As + kk * 128 + ty * 8);
            *(float4*)(a + 4) = *(const float4*)(As + kk * 128 + ty * 8 + 4);
            *(float4*)(b)     = *(const float4*)(Bs + kk * 128 + tx * 8);
            *(float4*)(b + 4) = *(const float4*)(Bs + kk * 128 + tx * 8 + 4);
#pragma unroll
            for (int i = 0; i < 8; i++)
#pragma unroll
                for (int j = 0; j < 8; j++) acc[i][j] = fmaf(a[i], b[j], acc[i][j]);
        }
        __syncthreads();
    }

    // fused epilogue: + U[src] + V[dst] + b1, relu, dot with W2, lane-reduce
    float w2v[8], b1v[8];
    {
        const float* wp = W2 + n0 + tx * 8;
        const float* bp = b1 + n0 + tx * 8;
#pragma unroll
        for (int j = 0; j < 8; j++) { w2v[j] = wp[j]; b1v[j] = bp[j]; }
    }
#pragma unroll
    for (int i = 0; i < 8; i++) {
        int mi = ty * 8 + i;
        const float* up = g_UV + (size_t)ssrc[mi] * (2 * H) + n0 + tx * 8;
        const float* vp = g_UV + (size_t)sdst[mi] * (2 * H) + H + n0 + tx * 8;
        float4 u0 = *(const float4*)(up);
        float4 u1 = *(const float4*)(up + 4);
        float4 v0 = *(const float4*)(vp);
        float4 v1 = *(const float4*)(vp + 4);
        float uv[8] = { u0.x + v0.x, u0.y + v0.y, u0.z + v0.z, u0.w + v0.w,
                        u1.x + v1.x, u1.y + v1.y, u1.z + v1.z, u1.w + v1.w };
        float partial = 0.f;
#pragma unroll
        for (int j = 0; j < 8; j++) {
            float h = acc[i][j] + uv[j] + b1v[j];
            h = fmaxf(h, 0.f);
            partial = fmaf(h, w2v[j], partial);
        }
        // lanes (ty%2)*16 + tx : xor 8/4/2/1 reduces across tx within each 16-lane half
        partial += __shfl_xor_sync(0xffffffffu, partial, 8);
        partial += __shfl_xor_sync(0xffffffffu, partial, 4);
        partial += __shfl_xor_sync(0xffffffffu, partial, 2);
        partial += __shfl_xor_sync(0xffffffffu, partial, 1);
        if (tx == 0)
            g_partial[(size_t)blockIdx.y * NPAIRS + p0 + mi] = partial;
    }
}

// ---------------- kernel D: sum partials + sigmoid ---------------------------
__global__ void finalize_kernel(const float* __restrict__ b2, float* __restrict__ out) {
    int p = blockIdx.x * blockDim.x + threadIdx.x;
    if (p >= NPAIRS) return;
    float z = g_partial[p] + g_partial[NPAIRS + p] +
              g_partial[2 * NPAIRS + p] + g_partial[3 * NPAIRS + p] + b2[0];
    out[p] = 1.f / (1.f + expf(-z));
}

// ---------------- launch -----------------------------------------------------
extern "C" void kernel_launch(void* const* d_in, const int* in_sizes, int n_in,
                              void* d_out, int out_size) {
    // inputs: 0=current_features (unused), 1=context_embeddings, 2=relationships,
    //         3=W1, 4=b1, 5=W2, 6=b2
    const float* E   = (const float*)d_in[1];
    const int*   rel = (const int*)  d_in[2];
    const float* W1  = (const float*)d_in[3];
    const float* b1  = (const float*)d_in[4];
    const float* W2  = (const float*)d_in[5];
    const float* b2  = (const float*)d_in[6];
    float* out = (float*)d_out;

    combine_w1<<<(H * H + 255) / 256, 256>>>(W1);
    uv_gemm<<<dim3(NDRONES / 128, (2 * H) / 128), 256>>>(E);
    pair_kernel<<<dim3(NPAIRS / 128, H / 128), 256>>>(E, rel, W1, b1, W2);
    finalize_kernel<<<NPAIRS / 256, 256>>>(b2, out);
}

// round 3
// speedup vs baseline: 1.8574x; 1.8574x over previous
#include <cuda_runtime.h>
#include <cuda_bf16.h>
#include <math.h>
#include <stdint.h>

#define H        512
#define NDRONES  16384
#define NPAIRS   131072

// ---------------- device scratch ---------------------------------------------
__device__ __nv_bfloat16 g_Wth[H * H];          // W1d^T hi  [n][k]
__device__ __nv_bfloat16 g_Wtl[H * H];          // W1d^T lo
__device__ __nv_bfloat16 g_ABth[2 * H * H];     // [A^T;B^T] hi [n=0..1023][k]
__device__ __nv_bfloat16 g_ABtl[2 * H * H];
__device__ float g_UV[(size_t)NDRONES * 2 * H]; // row i = [U_i(512) | V_i(512)]
__device__ float g_partial[4 * NPAIRS];

// ---------------- helpers ----------------------------------------------------
__device__ __forceinline__ uint32_t smem_u32(const void* p) {
    uint32_t a;
    asm("{ .reg .u64 t; cvta.to.shared.u64 t, %1; cvt.u32.u64 %0, t; }" : "=r"(a) : "l"(p));
    return a;
}
#define SW64(o) ((o) ^ (((o) >> 3) & 0x30))

__device__ __forceinline__ void ldsm_x4(uint32_t* r, uint32_t addr) {
    asm volatile("ldmatrix.sync.aligned.m8n8.x4.shared.b16 {%0,%1,%2,%3}, [%4];"
        : "=r"(r[0]), "=r"(r[1]), "=r"(r[2]), "=r"(r[3]) : "r"(addr));
}
__device__ __forceinline__ void ldsm_x2(uint32_t* r, uint32_t addr) {
    asm volatile("ldmatrix.sync.aligned.m8n8.x2.shared.b16 {%0,%1}, [%2];"
        : "=r"(r[0]), "=r"(r[1]) : "r"(addr));
}
__device__ __forceinline__ void mma_bf16(float* c, const uint32_t* a, const uint32_t* b) {
    asm volatile("mma.sync.aligned.m16n8k16.row.col.f32.bf16.bf16.f32 "
        "{%0,%1,%2,%3}, {%4,%5,%6,%7}, {%8,%9}, {%0,%1,%2,%3};"
        : "+f"(c[0]), "+f"(c[1]), "+f"(c[2]), "+f"(c[3])
        : "r"(a[0]), "r"(a[1]), "r"(a[2]), "r"(a[3]), "r"(b[0]), "r"(b[1]));
}

// split 8 fp32 -> 4x bf16x2 hi + 4x bf16x2 lo
__device__ __forceinline__ void split8(const float* p, uint32_t* hi, uint32_t* lo) {
#pragma unroll
    for (int j = 0; j < 4; ++j) {
        float2 pp = make_float2(p[2 * j], p[2 * j + 1]);
        __nv_bfloat162 h2 = __float22bfloat162_rn(pp);
        float2 hf = __bfloat1622float2(h2);
        __nv_bfloat162 l2 = __float22bfloat162_rn(make_float2(pp.x - hf.x, pp.y - hf.y));
        hi[j] = *reinterpret_cast<uint32_t*>(&h2);
        lo[j] = *reinterpret_cast<uint32_t*>(&l2);
    }
}

// ---------------- SMEM layout ------------------------------------------------
// staging (chunk): A_hi 8K | A_lo 8K | B_hi 8K | B_lo 8K   (reused by C epilogue)
#define SM_AHI   0
#define SM_ALO   8192
#define SM_BHI   16384
#define SM_BLO   24576
#define CSTRIDE  132                       // fp32 stride for 128-wide C rows
#define SM_CEND  (128 * CSTRIDE * 4)       // 67584
#define SM_SRC   68608
#define SM_DST   69120
#define SM_B1V   69632
#define SM_W2V   70144
#define SMEM_TOTAL 71680

// ================= GEMM engine (shared by pair & uv) =========================
// One chunk: build A/B tiles in smem (bf16 hi/lo, SW64), then warp-MMA.
struct Frag { uint32_t aA[4][2], aB[4][2]; };  // ldmatrix addresses (hi buffers)

__device__ __forceinline__ void make_addrs(Frag& f, uint32_t sb, int warp, int lane) {
    int wM0 = (warp >> 2) * 64, wN0 = (warp & 3) * 32;
#pragma unroll
    for (int mt = 0; mt < 4; ++mt)
#pragma unroll
        for (int kh = 0; kh < 2; ++kh) {
            uint32_t row = wM0 + mt * 16 + (lane & 15);
            uint32_t byo = row * 64 + kh * 32 + (lane >> 4) * 16;
            f.aA[mt][kh] = sb + SM_AHI + SW64(byo);
        }
#pragma unroll
    for (int nt = 0; nt < 4; ++nt)
#pragma unroll
        for (int kh = 0; kh < 2; ++kh) {
            uint32_t row = wN0 + nt * 8 + (lane & 7);
            uint32_t byo = row * 64 + kh * 32 + ((lane >> 3) & 1) * 16;
            f.aB[nt][kh] = sb + SM_BHI + SW64(byo);
        }
}

__device__ __forceinline__ void mma_chunk(const Frag& f, float c[4][4][4]) {
#pragma unroll
    for (int kh = 0; kh < 2; ++kh) {
        uint32_t ah[4][4], al[4][4], bh[4][2], bl[4][2];
#pragma unroll
        for (int mt = 0; mt < 4; ++mt) {
            ldsm_x4(ah[mt], f.aA[mt][kh]);
            ldsm_x4(al[mt], f.aA[mt][kh] + 8192);
        }
#pragma unroll
        for (int nt = 0; nt < 4; ++nt) {
            ldsm_x2(bh[nt], f.aB[nt][kh]);
            ldsm_x2(bl[nt], f.aB[nt][kh] + 8192);
        }
#pragma unroll
        for (int mt = 0; mt < 4; ++mt)
#pragma unroll
            for (int nt = 0; nt < 4; ++nt) {
                mma_bf16(c[mt][nt], ah[mt], bh[nt]);
                mma_bf16(c[mt][nt], al[mt], bh[nt]);
                mma_bf16(c[mt][nt], ah[mt], bl[nt]);
            }
    }
}

// store 16 fp32 (as hi/lo bf16) into A smem at (row, halfk)
__device__ __forceinline__ void store_a(char* smem, int row, int halfk, const float* pr) {
    uint32_t hi[8], lo[8];
    split8(pr, hi, lo);
    split8(pr + 8, hi + 4, lo + 4);
    uint32_t b0 = row * 64 + halfk * 32;
    *(uint4*)(smem + SM_AHI + SW64(b0))      = make_uint4(hi[0], hi[1], hi[2], hi[3]);
    *(uint4*)(smem + SM_AHI + SW64(b0 + 16)) = make_uint4(hi[4], hi[5], hi[6], hi[7]);
    *(uint4*)(smem + SM_ALO + SW64(b0))      = make_uint4(lo[0], lo[1], lo[2], lo[3]);
    *(uint4*)(smem + SM_ALO + SW64(b0 + 16)) = make_uint4(lo[4], lo[5], lo[6], lo[7]);
}
__device__ __forceinline__ void store_b(char* smem, int row, int halfk,
                                        uint4 wh0, uint4 wh1, uint4 wl0, uint4 wl1) {
    uint32_t b0 = row * 64 + halfk * 32;
    *(uint4*)(smem + SM_BHI + SW64(b0))      = wh0;
    *(uint4*)(smem + SM_BHI + SW64(b0 + 16)) = wh1;
    *(uint4*)(smem + SM_BLO + SW64(b0))      = wl0;
    *(uint4*)(smem + SM_BLO + SW64(b0 + 16)) = wl1;
}

// accum frags -> smem C[128][CSTRIDE]
__device__ __forceinline__ void c_to_smem(float* Cs, const float c[4][4][4], int warp, int lane) {
    int wM0 = (warp >> 2) * 64, wN0 = (warp & 3) * 32;
#pragma unroll
    for (int mt = 0; mt < 4; ++mt)
#pragma unroll
        for (int nt = 0; nt < 4; ++nt) {
            int r = wM0 + mt * 16 + (lane >> 2);
            int cc = wN0 + nt * 8 + (lane & 3) * 2;
            *(float2*)(Cs + r * CSTRIDE + cc)       = make_float2(c[mt][nt][0], c[mt][nt][1]);
            *(float2*)(Cs + (r + 8) * CSTRIDE + cc) = make_float2(c[mt][nt][2], c[mt][nt][3]);
        }
}

// ---------------- prep kernels -----------------------------------------------
__global__ void prep_wd(const float* __restrict__ W1) {
    __shared__ float tile[32][33];
    int kb = blockIdx.x * 32, nb = blockIdx.y * 32;
    int tx = threadIdx.x, ty = threadIdx.y;
    for (int r = ty; r < 32; r += 8)
        tile[r][tx] = W1[(size_t)(3 * H + kb + r) * H + nb + tx];
    __syncthreads();
    for (int r = ty; r < 32; r += 8) {
        float v = tile[tx][r];
        __nv_bfloat16 h = __float2bfloat16(v);
        g_Wth[(size_t)(nb + r) * H + kb + tx] = h;
        g_Wtl[(size_t)(nb + r) * H + kb + tx] = __float2bfloat16(v - __bfloat162float(h));
    }
}
__global__ void prep_ab(const float* __restrict__ W1) {
    __shared__ float tile[32][33];
    int kb = blockIdx.x * 32, nb = blockIdx.y * 32;   // nb in [0,1024)
    int tx = threadIdx.x, ty = threadIdx.y;
    bool isv = (nb >= H);
    int nn = isv ? (nb - H) + tx : nb + tx;
    for (int r = ty; r < 32; r += 8) {
        int k = kb + r;
        float wc = W1[(size_t)(2 * H + k) * H + nn];
        float v = isv ? (W1[(size_t)(H + k) * H + nn] + wc)
                      : (W1[(size_t)k * H + nn] - wc);
        tile[r][tx] = v;
    }
    __syncthreads();
    for (int r = ty; r < 32; r += 8) {
        float v = tile[tx][r];
        __nv_bfloat16 h = __float2bfloat16(v);
        g_ABth[(size_t)(nb + r) * H + kb + tx] = h;
        g_ABtl[(size_t)(nb + r) * H + kb + tx] = __float2bfloat16(v - __bfloat162float(h));
    }
}

// ---------------- UV = E @ [A|B]  (tensor path) ------------------------------
__global__ void __launch_bounds__(256, 1) uv_mma(const float* __restrict__ E) {
    extern __shared__ __align__(1024) char smem[];
    uint32_t sb = smem_u32(smem);
    int t = threadIdx.x, warp = t >> 5, lane = t & 31;
    int m0 = blockIdx.x * 128, n0 = blockIdx.y * 128;
    int row = t >> 1, halfk = t & 1;

    const float* erow = E + (size_t)(m0 + row) * H + halfk * 16;
    const __nv_bfloat16* wh = g_Wth; (void)wh;
    const __nv_bfloat16* bhp = g_ABth + (size_t)(n0 + row) * H + halfk * 16;
    const __nv_bfloat16* blp = g_ABtl + (size_t)(n0 + row) * H + halfk * 16;

    Frag f; make_addrs(f, sb, warp, lane);
    float c[4][4][4];
#pragma unroll
    for (int a = 0; a < 4; ++a)
#pragma unroll
        for (int b = 0; b < 4; ++b)
#pragma unroll
            for (int d = 0; d < 4; ++d) c[a][b][d] = 0.f;

    float ev[16];
    uint4 wh0, wh1, wl0, wl1;
    *(float4*)(ev)      = *(const float4*)(erow + 0);
    *(float4*)(ev + 4)  = *(const float4*)(erow + 4);
    *(float4*)(ev + 8)  = *(const float4*)(erow + 8);
    *(float4*)(ev + 12) = *(const float4*)(erow + 12);
    wh0 = *(const uint4*)(bhp);     wh1 = *(const uint4*)(bhp + 8);
    wl0 = *(const uint4*)(blp);     wl1 = *(const uint4*)(blp + 8);

    for (int ch = 0; ch < 16; ++ch) {
        store_a(smem, row, halfk, ev);
        store_b(smem, row, halfk, wh0, wh1, wl0, wl1);
        __syncthreads();
        if (ch < 15) {
            int k0 = (ch + 1) * 32;
            *(float4*)(ev)      = *(const float4*)(erow + k0);
            *(float4*)(ev + 4)  = *(const float4*)(erow + k0 + 4);
            *(float4*)(ev + 8)  = *(const float4*)(erow + k0 + 8);
            *(float4*)(ev + 12) = *(const float4*)(erow + k0 + 12);
            wh0 = *(const uint4*)(bhp + k0);     wh1 = *(const uint4*)(bhp + k0 + 8);
            wl0 = *(const uint4*)(blp + k0);     wl1 = *(const uint4*)(blp + k0 + 8);
        }
        mma_chunk(f, c);
        __syncthreads();
    }

    float* Cs = (float*)smem;
    c_to_smem(Cs, c, warp, lane);
    __syncthreads();
    // write coalesced to g_UV
    float* dst = g_UV + (size_t)(m0 + row) * (2 * H) + n0 + halfk * 64;
    const float* srcrow = Cs + row * CSTRIDE + halfk * 64;
#pragma unroll
    for (int j = 0; j < 64; j += 4)
        *(float4*)(dst + j) = *(const float4*)(srcrow + j);
}

// ---------------- pair kernel ------------------------------------------------
__global__ void __launch_bounds__(256, 1) pair_mma(
    const float* __restrict__ E, const int* __restrict__ rel,
    const float* __restrict__ b1, const float* __restrict__ W2)
{
    extern __shared__ __align__(1024) char smem[];
    uint32_t sb = smem_u32(smem);
    int t = threadIdx.x, warp = t >> 5, lane = t & 31;
    int p0 = blockIdx.x * 128, n0 = blockIdx.y * 128;
    int row = t >> 1, halfk = t & 1;

    int* ssrc = (int*)(smem + SM_SRC);
    int* sdst = (int*)(smem + SM_DST);
    float* b1s = (float*)(smem + SM_B1V);
    float* w2s = (float*)(smem + SM_W2V);
    if (t < 128) {
        ssrc[t] = rel[(size_t)(p0 + t) * 2 + 0];
        sdst[t] = rel[(size_t)(p0 + t) * 2 + 1];
        b1s[t] = b1[n0 + t];
        w2s[t] = W2[n0 + t];
    }
    __syncthreads();

    const float* srow = E + (size_t)ssrc[row] * H + halfk * 16;
    const float* drow = E + (size_t)sdst[row] * H + halfk * 16;
    const __nv_bfloat16* bhp = g_Wth + (size_t)(n0 + row) * H + halfk * 16;
    const __nv_bfloat16* blp = g_Wtl + (size_t)(n0 + row) * H + halfk * 16;

    Frag f; make_addrs(f, sb, warp, lane);
    float c[4][4][4];
#pragma unroll
    for (int a = 0; a < 4; ++a)
#pragma unroll
        for (int b = 0; b < 4; ++b)
#pragma unroll
            for (int d = 0; d < 4; ++d) c[a][b][d] = 0.f;

    float sv[16], dv[16];
    uint4 wh0, wh1, wl0, wl1;
    *(float4*)(sv)      = *(const float4*)(srow + 0);
    *(float4*)(sv + 4)  = *(const float4*)(srow + 4);
    *(float4*)(sv + 8)  = *(const float4*)(srow + 8);
    *(float4*)(sv + 12) = *(const float4*)(srow + 12);
    *(float4*)(dv)      = *(const float4*)(drow + 0);
    *(float4*)(dv + 4)  = *(const float4*)(drow + 4);
    *(float4*)(dv + 8)  = *(const float4*)(drow + 8);
    *(float4*)(dv + 12) = *(const float4*)(drow + 12);
    wh0 = *(const uint4*)(bhp);     wh1 = *(const uint4*)(bhp + 8);
    wl0 = *(const uint4*)(blp);     wl1 = *(const uint4*)(blp + 8);

    for (int ch = 0; ch < 16; ++ch) {
        float pr[16];
#pragma unroll
        for (int j = 0; j < 16; ++j) pr[j] = sv[j] * dv[j];
        store_a(smem, row, halfk, pr);
        store_b(smem, row, halfk, wh0, wh1, wl0, wl1);
        __syncthreads();
        if (ch < 15) {
            int k0 = (ch + 1) * 32;
            *(float4*)(sv)      = *(const float4*)(srow + k0);
            *(float4*)(sv + 4)  = *(const float4*)(srow + k0 + 4);
            *(float4*)(sv + 8)  = *(const float4*)(srow + k0 + 8);
            *(float4*)(sv + 12) = *(const float4*)(srow + k0 + 12);
            *(float4*)(dv)      = *(const float4*)(drow + k0);
            *(float4*)(dv + 4)  = *(const float4*)(drow + k0 + 4);
            *(float4*)(dv + 8)  = *(const float4*)(drow + k0 + 8);
            *(float4*)(dv + 12) = *(const float4*)(drow + k0 + 12);
            wh0 = *(const uint4*)(bhp + k0);     wh1 = *(const uint4*)(bhp + k0 + 8);
            wl0 = *(const uint4*)(blp + k0);     wl1 = *(const uint4*)(blp + k0 + 8);
        }
        mma_chunk(f, c);
        __syncthreads();
    }

    float* Cs = (float*)smem;
    c_to_smem(Cs, c, warp, lane);
    __syncthreads();

    // epilogue: relu(C + U[src] + V[dst] + b1) . W2  over this n-block
    {
        int nh = halfk * 64;
        const float* crow = Cs + row * CSTRIDE + nh;
        const float* urow = g_UV + (size_t)ssrc[row] * (2 * H) + n0 + nh;
        const float* vrow = g_UV + (size_t)sdst[row] * (2 * H) + H + n0 + nh;
        float partial = 0.f;
#pragma unroll
        for (int j = 0; j < 64; j += 4) {
            float4 cc = *(const float4*)(crow + j);
            float4 u  = *(const float4*)(urow + j);
            float4 v  = *(const float4*)(vrow + j);
            float h0 = cc.x + u.x + v.x + b1s[nh + j + 0];
            float h1 = cc.y + u.y + v.y + b1s[nh + j + 1];
            float h2 = cc.z + u.z + v.z + b1s[nh + j + 2];
            float h3 = cc.w + u.w + v.w + b1s[nh + j + 3];
            partial = fmaf(fmaxf(h0, 0.f), w2s[nh + j + 0], partial);
            partial = fmaf(fmaxf(h1, 0.f), w2s[nh + j + 1], partial);
            partial = fmaf(fmaxf(h2, 0.f), w2s[nh + j + 2], partial);
            partial = fmaf(fmaxf(h3, 0.f), w2s[nh + j + 3], partial);
        }
        partial += __shfl_xor_sync(0xffffffffu, partial, 1);
        if (halfk == 0)
            g_partial[(size_t)blockIdx.y * NPAIRS + p0 + row] = partial;
    }
}

// ---------------- finalize ---------------------------------------------------
__global__ void finalize_kernel(const float* __restrict__ b2, float* __restrict__ out) {
    int p = blockIdx.x * blockDim.x + threadIdx.x;
    if (p >= NPAIRS) return;
    float z = g_partial[p] + g_partial[NPAIRS + p] +
              g_partial[2 * NPAIRS + p] + g_partial[3 * NPAIRS + p] + b2[0];
    out[p] = 1.f / (1.f + expf(-z));
}

// ---------------- launch -----------------------------------------------------
extern "C" void kernel_launch(void* const* d_in, const int* in_sizes, int n_in,
                              void* d_out, int out_size) {
    const float* E   = (const float*)d_in[1];
    const int*   rel = (const int*)  d_in[2];
    const float* W1  = (const float*)d_in[3];
    const float* b1  = (const float*)d_in[4];
    const float* W2  = (const float*)d_in[5];
    const float* b2  = (const float*)d_in[6];
    float* out = (float*)d_out;

    cudaFuncSetAttribute(uv_mma, cudaFuncAttributeMaxDynamicSharedMemorySize, SMEM_TOTAL);
    cudaFuncSetAttribute(pair_mma, cudaFuncAttributeMaxDynamicSharedMemorySize, SMEM_TOTAL);

    prep_wd<<<dim3(16, 16), dim3(32, 8)>>>(W1);
    prep_ab<<<dim3(16, 32), dim3(32, 8)>>>(W1);
    uv_mma<<<dim3(NDRONES / 128, 8), 256, SMEM_TOTAL>>>(E);
    pair_mma<<<dim3(NPAIRS / 128, 4), 256, SMEM_TOTAL>>>(E, rel, b1, W2);
    finalize_kernel<<<NPAIRS / 256, 256>>>(b2, out);
}